// round 2
// baseline (speedup 1.0000x reference)
#include <cuda_runtime.h>

// One warp per edge. Lane i handles elements [2i, 2i+1] of the 64-dim row.
// Fused reductions for distance^2 and K.Q via shfl butterfly; single __expf.
// NOTE: indices are int32 on device (JAX x64-disabled downcasts jnp.int64).
__global__ void __launch_bounds__(256) rpm_kernel(
    const float* __restrict__ G,
    const float* __restrict__ K,
    const float* __restrict__ Q,
    const float* __restrict__ V,
    const int* __restrict__ src,
    const int* __restrict__ dst,
    float* __restrict__ out,
    int n_edges,
    int n_nodes)
{
    int gwarp = (blockIdx.x * blockDim.x + threadIdx.x) >> 5;
    int lane  = threadIdx.x & 31;
    if (gwarp >= n_edges) return;

    int s = src[gwarp];
    int d = dst[gwarp];
    // defensive clamp: if dtype assumption is ever wrong we get a wrong
    // answer (diagnosable) instead of an illegal access (opaque).
    s = min(max(s, 0), n_nodes - 1);
    d = min(max(d, 0), n_nodes - 1);

    const float2* Gs = reinterpret_cast<const float2*>(G + (size_t)s * 64);
    const float2* Gd = reinterpret_cast<const float2*>(G + (size_t)d * 64);
    const float2* Ks = reinterpret_cast<const float2*>(K + (size_t)s * 64);
    const float2* Qd = reinterpret_cast<const float2*>(Q + (size_t)d * 64);
    const float2* Vs = reinterpret_cast<const float2*>(V + (size_t)s * 64);

    float2 gs = Gs[lane];
    float2 gd = Gd[lane];
    float2 ks = Ks[lane];
    float2 qd = Qd[lane];
    float2 vs = Vs[lane];

    float dx = gs.x - gd.x;
    float dy = gs.y - gd.y;
    float pd = dx * dx + dy * dy;           // partial |diff|^2
    float pk = ks.x * qd.x + ks.y * qd.y;   // partial K.Q

    #pragma unroll
    for (int off = 16; off > 0; off >>= 1) {
        pd += __shfl_xor_sync(0xFFFFFFFFu, pd, off);
        pk += __shfl_xor_sync(0xFFFFFFFFu, pk, off);
    }

    const float inv_sqrt_d = 0.125f;  // 1/sqrt(64)
    float a = -sqrtf(pd + 1e-6f) * inv_sqrt_d;
    a = fminf(fmaxf(a, -5.0f), 5.0f);
    float b = pk * inv_sqrt_d;
    b = fminf(fmaxf(b, -5.0f), 5.0f);
    float w = __expf(a + b);

    float2 o;
    o.x = w * vs.x;
    o.y = w * vs.y;
    reinterpret_cast<float2*>(out)[(size_t)gwarp * 32 + lane] = o;
}

extern "C" void kernel_launch(void* const* d_in, const int* in_sizes, int n_in,
                              void* d_out, int out_size) {
    const float* G = (const float*)d_in[0];
    const float* K = (const float*)d_in[1];
    const float* Q = (const float*)d_in[2];
    const float* V = (const float*)d_in[3];
    const int* src = (const int*)d_in[4];
    const int* dst = (const int*)d_in[5];
    float* out = (float*)d_out;

    int n_edges = in_sizes[4];       // src element count
    int n_nodes = in_sizes[0] / 64;  // G_h rows
    int warps_per_block = 256 / 32;
    int blocks = (n_edges + warps_per_block - 1) / warps_per_block;
    rpm_kernel<<<blocks, 256>>>(G, K, Q, V, src, dst, out, n_edges, n_nodes);
}

// round 3
// speedup vs baseline: 1.5997x; 1.5997x over previous
#include <cuda_runtime.h>

// 16 lanes per edge, float4 per lane (16 x 16B = 64 floats). Two edges per
// warp: every LDG.128/SHFL/STG.128 serves both edges, halving issue count
// vs the one-warp-per-edge version. Reduction is a 4-step shfl butterfly
// confined to each 16-lane half.
__global__ void __launch_bounds__(256) rpm_kernel(
    const float* __restrict__ G,
    const float* __restrict__ K,
    const float* __restrict__ Q,
    const float* __restrict__ V,
    const int* __restrict__ src,
    const int* __restrict__ dst,
    float* __restrict__ out,
    int n_edges,
    int n_nodes)
{
    int sub   = threadIdx.x >> 4;                       // 16-lane group in block
    int lane  = threadIdx.x & 15;
    int e     = blockIdx.x * (blockDim.x >> 4) + sub;   // edge id
    bool live = (e < n_edges);
    e = min(e, n_edges - 1);                            // keep all lanes active for shfl

    int s = src[e];
    int d = dst[e];
    s = min(max(s, 0), n_nodes - 1);
    d = min(max(d, 0), n_nodes - 1);

    const float4* Gs = reinterpret_cast<const float4*>(G + (size_t)s * 64);
    const float4* Gd = reinterpret_cast<const float4*>(G + (size_t)d * 64);
    const float4* Ks = reinterpret_cast<const float4*>(K + (size_t)s * 64);
    const float4* Qd = reinterpret_cast<const float4*>(Q + (size_t)d * 64);
    const float4* Vs = reinterpret_cast<const float4*>(V + (size_t)s * 64);

    float4 gs = Gs[lane];
    float4 gd = Gd[lane];
    float4 ks = Ks[lane];
    float4 qd = Qd[lane];
    float4 vs = Vs[lane];

    float dx = gs.x - gd.x, dy = gs.y - gd.y,
          dz = gs.z - gd.z, dw = gs.w - gd.w;
    float pd = dx * dx + dy * dy + dz * dz + dw * dw;            // partial |diff|^2
    float pk = ks.x * qd.x + ks.y * qd.y + ks.z * qd.z + ks.w * qd.w;  // partial K.Q

    #pragma unroll
    for (int off = 8; off > 0; off >>= 1) {
        pd += __shfl_xor_sync(0xFFFFFFFFu, pd, off);
        pk += __shfl_xor_sync(0xFFFFFFFFu, pk, off);
    }

    const float inv_sqrt_d = 0.125f;  // 1/sqrt(64)
    float a = -sqrtf(pd + 1e-6f) * inv_sqrt_d;
    a = fminf(fmaxf(a, -5.0f), 5.0f);
    float b = pk * inv_sqrt_d;
    b = fminf(fmaxf(b, -5.0f), 5.0f);
    float w = __expf(a + b);

    if (live) {
        float4 o;
        o.x = w * vs.x;
        o.y = w * vs.y;
        o.z = w * vs.z;
        o.w = w * vs.w;
        reinterpret_cast<float4*>(out)[(size_t)e * 16 + lane] = o;
    }
}

extern "C" void kernel_launch(void* const* d_in, const int* in_sizes, int n_in,
                              void* d_out, int out_size) {
    const float* G = (const float*)d_in[0];
    const float* K = (const float*)d_in[1];
    const float* Q = (const float*)d_in[2];
    const float* V = (const float*)d_in[3];
    const int* src = (const int*)d_in[4];
    const int* dst = (const int*)d_in[5];
    float* out = (float*)d_out;

    int n_edges = in_sizes[4];       // src element count
    int n_nodes = in_sizes[0] / 64;  // G_h rows
    int edges_per_block = 256 / 16;
    int blocks = (n_edges + edges_per_block - 1) / edges_per_block;
    rpm_kernel<<<blocks, 256>>>(G, K, Q, V, src, dst, out, n_edges, n_nodes);
}

// round 4
// speedup vs baseline: 1.6802x; 1.0503x over previous
#include <cuda_runtime.h>

// 16 lanes per edge-slot, float4 per lane. Each 16-lane group processes TWO
// consecutive edges with all 10 gather LDG.128s issued before any reduction
// (2x MLP vs R3). Output uses streaming stores (__stwt) so the 256MB write
// stream doesn't evict the 51MB node tables from L2.
__global__ void __launch_bounds__(256) rpm_kernel(
    const float* __restrict__ G,
    const float* __restrict__ K,
    const float* __restrict__ Q,
    const float* __restrict__ V,
    const int* __restrict__ src,
    const int* __restrict__ dst,
    float* __restrict__ out,
    int n_edges,
    int n_nodes)
{
    int sub  = threadIdx.x >> 4;                         // 16-lane group in block
    int lane = threadIdx.x & 15;
    int g    = blockIdx.x * (blockDim.x >> 4) + sub;     // group id
    int e0   = 2 * g;
    int e1   = 2 * g + 1;
    bool live0 = (e0 < n_edges);
    bool live1 = (e1 < n_edges);
    int ec0 = min(e0, n_edges - 1);
    int ec1 = min(e1, n_edges - 1);

    int s0 = min(max(src[ec0], 0), n_nodes - 1);
    int d0 = min(max(dst[ec0], 0), n_nodes - 1);
    int s1 = min(max(src[ec1], 0), n_nodes - 1);
    int d1 = min(max(dst[ec1], 0), n_nodes - 1);

    const float4* G4 = reinterpret_cast<const float4*>(G);
    const float4* K4 = reinterpret_cast<const float4*>(K);
    const float4* Q4 = reinterpret_cast<const float4*>(Q);
    const float4* V4 = reinterpret_cast<const float4*>(V);

    // Batch all 10 gathers up front for maximum MLP.
    float4 gs0 = G4[(size_t)s0 * 16 + lane];
    float4 gd0 = G4[(size_t)d0 * 16 + lane];
    float4 ks0 = K4[(size_t)s0 * 16 + lane];
    float4 qd0 = Q4[(size_t)d0 * 16 + lane];
    float4 vs0 = V4[(size_t)s0 * 16 + lane];
    float4 gs1 = G4[(size_t)s1 * 16 + lane];
    float4 gd1 = G4[(size_t)d1 * 16 + lane];
    float4 ks1 = K4[(size_t)s1 * 16 + lane];
    float4 qd1 = Q4[(size_t)d1 * 16 + lane];
    float4 vs1 = V4[(size_t)s1 * 16 + lane];

    float dx, dy, dz, dw;
    dx = gs0.x - gd0.x; dy = gs0.y - gd0.y; dz = gs0.z - gd0.z; dw = gs0.w - gd0.w;
    float pd0 = dx * dx + dy * dy + dz * dz + dw * dw;
    float pk0 = ks0.x * qd0.x + ks0.y * qd0.y + ks0.z * qd0.z + ks0.w * qd0.w;

    dx = gs1.x - gd1.x; dy = gs1.y - gd1.y; dz = gs1.z - gd1.z; dw = gs1.w - gd1.w;
    float pd1 = dx * dx + dy * dy + dz * dz + dw * dw;
    float pk1 = ks1.x * qd1.x + ks1.y * qd1.y + ks1.z * qd1.z + ks1.w * qd1.w;

    #pragma unroll
    for (int off = 8; off > 0; off >>= 1) {
        pd0 += __shfl_xor_sync(0xFFFFFFFFu, pd0, off);
        pk0 += __shfl_xor_sync(0xFFFFFFFFu, pk0, off);
        pd1 += __shfl_xor_sync(0xFFFFFFFFu, pd1, off);
        pk1 += __shfl_xor_sync(0xFFFFFFFFu, pk1, off);
    }

    const float inv_sqrt_d = 0.125f;  // 1/sqrt(64)

    float a0 = fminf(fmaxf(-sqrtf(pd0 + 1e-6f) * inv_sqrt_d, -5.0f), 5.0f);
    float b0 = fminf(fmaxf(pk0 * inv_sqrt_d, -5.0f), 5.0f);
    float w0 = __expf(a0 + b0);

    float a1 = fminf(fmaxf(-sqrtf(pd1 + 1e-6f) * inv_sqrt_d, -5.0f), 5.0f);
    float b1 = fminf(fmaxf(pk1 * inv_sqrt_d, -5.0f), 5.0f);
    float w1 = __expf(a1 + b1);

    float4* out4 = reinterpret_cast<float4*>(out);
    if (live0) {
        float4 o = make_float4(w0 * vs0.x, w0 * vs0.y, w0 * vs0.z, w0 * vs0.w);
        __stwt(&out4[(size_t)e0 * 16 + lane], o);
    }
    if (live1) {
        float4 o = make_float4(w1 * vs1.x, w1 * vs1.y, w1 * vs1.z, w1 * vs1.w);
        __stwt(&out4[(size_t)e1 * 16 + lane], o);
    }
}

extern "C" void kernel_launch(void* const* d_in, const int* in_sizes, int n_in,
                              void* d_out, int out_size) {
    const float* G = (const float*)d_in[0];
    const float* K = (const float*)d_in[1];
    const float* Q = (const float*)d_in[2];
    const float* V = (const float*)d_in[3];
    const int* src = (const int*)d_in[4];
    const int* dst = (const int*)d_in[5];
    float* out = (float*)d_out;

    int n_edges = in_sizes[4];       // src element count
    int n_nodes = in_sizes[0] / 64;  // G_h rows
    int groups_per_block = 256 / 16;           // 16 groups
    int edges_per_block = groups_per_block * 2; // 32 edges
    int blocks = (n_edges + edges_per_block - 1) / edges_per_block;
    rpm_kernel<<<blocks, 256>>>(G, K, Q, V, src, dst, out, n_edges, n_nodes);
}

// round 5
// speedup vs baseline: 1.7487x; 1.0408x over previous
#include <cuda_runtime.h>
#include <cstdint>

// Gather loads use an L2 evict_last cache policy (node tables ~51MB pinned in
// the 126MB L2); output uses streaming evict-first stores (__stcs) so the
// 256MB write stream doesn't evict them. 16 lanes per edge-slot, float4 per
// lane, two edges per group with all 10 gathers batched for MLP.

__device__ __forceinline__ float4 ldg_el(const float* p, uint64_t pol) {
    float4 v;
    asm volatile(
        "ld.global.nc.L2::cache_hint.v4.f32 {%0,%1,%2,%3}, [%4], %5;"
        : "=f"(v.x), "=f"(v.y), "=f"(v.z), "=f"(v.w)
        : "l"(p), "l"(pol));
    return v;
}

__global__ void __launch_bounds__(256) rpm_kernel(
    const float* __restrict__ G,
    const float* __restrict__ K,
    const float* __restrict__ Q,
    const float* __restrict__ V,
    const int* __restrict__ src,
    const int* __restrict__ dst,
    float* __restrict__ out,
    int n_edges,
    int n_nodes)
{
    uint64_t pol;
    asm("createpolicy.fractional.L2::evict_last.b64 %0, 1.0;" : "=l"(pol));

    int sub  = threadIdx.x >> 4;                       // 16-lane group in block
    int lane = threadIdx.x & 15;
    int g    = blockIdx.x * (blockDim.x >> 4) + sub;   // group id
    int e0   = 2 * g;
    int e1   = 2 * g + 1;
    bool live0 = (e0 < n_edges);
    bool live1 = (e1 < n_edges);
    int ec0 = min(e0, n_edges - 1);
    int ec1 = min(e1, n_edges - 1);

    int s0 = min(max(src[ec0], 0), n_nodes - 1);
    int d0 = min(max(dst[ec0], 0), n_nodes - 1);
    int s1 = min(max(src[ec1], 0), n_nodes - 1);
    int d1 = min(max(dst[ec1], 0), n_nodes - 1);

    size_t l4 = (size_t)lane * 4;

    // Batch all 10 gathers up front for maximum MLP; evict_last in L2.
    float4 gs0 = ldg_el(G + (size_t)s0 * 64 + l4, pol);
    float4 gd0 = ldg_el(G + (size_t)d0 * 64 + l4, pol);
    float4 ks0 = ldg_el(K + (size_t)s0 * 64 + l4, pol);
    float4 qd0 = ldg_el(Q + (size_t)d0 * 64 + l4, pol);
    float4 vs0 = ldg_el(V + (size_t)s0 * 64 + l4, pol);
    float4 gs1 = ldg_el(G + (size_t)s1 * 64 + l4, pol);
    float4 gd1 = ldg_el(G + (size_t)d1 * 64 + l4, pol);
    float4 ks1 = ldg_el(K + (size_t)s1 * 64 + l4, pol);
    float4 qd1 = ldg_el(Q + (size_t)d1 * 64 + l4, pol);
    float4 vs1 = ldg_el(V + (size_t)s1 * 64 + l4, pol);

    float dx, dy, dz, dw;
    dx = gs0.x - gd0.x; dy = gs0.y - gd0.y; dz = gs0.z - gd0.z; dw = gs0.w - gd0.w;
    float pd0 = dx * dx + dy * dy + dz * dz + dw * dw;
    float pk0 = ks0.x * qd0.x + ks0.y * qd0.y + ks0.z * qd0.z + ks0.w * qd0.w;

    dx = gs1.x - gd1.x; dy = gs1.y - gd1.y; dz = gs1.z - gd1.z; dw = gs1.w - gd1.w;
    float pd1 = dx * dx + dy * dy + dz * dz + dw * dw;
    float pk1 = ks1.x * qd1.x + ks1.y * qd1.y + ks1.z * qd1.z + ks1.w * qd1.w;

    #pragma unroll
    for (int off = 8; off > 0; off >>= 1) {
        pd0 += __shfl_xor_sync(0xFFFFFFFFu, pd0, off);
        pk0 += __shfl_xor_sync(0xFFFFFFFFu, pk0, off);
        pd1 += __shfl_xor_sync(0xFFFFFFFFu, pd1, off);
        pk1 += __shfl_xor_sync(0xFFFFFFFFu, pk1, off);
    }

    const float inv_sqrt_d = 0.125f;  // 1/sqrt(64)

    float a0 = fminf(fmaxf(-sqrtf(pd0 + 1e-6f) * inv_sqrt_d, -5.0f), 5.0f);
    float b0 = fminf(fmaxf(pk0 * inv_sqrt_d, -5.0f), 5.0f);
    float w0 = __expf(a0 + b0);

    float a1 = fminf(fmaxf(-sqrtf(pd1 + 1e-6f) * inv_sqrt_d, -5.0f), 5.0f);
    float b1 = fminf(fmaxf(pk1 * inv_sqrt_d, -5.0f), 5.0f);
    float w1 = __expf(a1 + b1);

    float4* out4 = reinterpret_cast<float4*>(out);
    if (live0) {
        float4 o = make_float4(w0 * vs0.x, w0 * vs0.y, w0 * vs0.z, w0 * vs0.w);
        __stcs(&out4[(size_t)e0 * 16 + lane], o);   // evict-first streaming store
    }
    if (live1) {
        float4 o = make_float4(w1 * vs1.x, w1 * vs1.y, w1 * vs1.z, w1 * vs1.w);
        __stcs(&out4[(size_t)e1 * 16 + lane], o);
    }
}

extern "C" void kernel_launch(void* const* d_in, const int* in_sizes, int n_in,
                              void* d_out, int out_size) {
    const float* G = (const float*)d_in[0];
    const float* K = (const float*)d_in[1];
    const float* Q = (const float*)d_in[2];
    const float* V = (const float*)d_in[3];
    const int* src = (const int*)d_in[4];
    const int* dst = (const int*)d_in[5];
    float* out = (float*)d_out;

    int n_edges = in_sizes[4];       // src element count
    int n_nodes = in_sizes[0] / 64;  // G_h rows
    int groups_per_block = 256 / 16;            // 16 groups
    int edges_per_block = groups_per_block * 2; // 32 edges
    int blocks = (n_edges + edges_per_block - 1) / edges_per_block;
    rpm_kernel<<<blocks, 256>>>(G, K, Q, V, src, dst, out, n_edges, n_nodes);
}

// round 6
// speedup vs baseline: 1.8381x; 1.0511x over previous
#include <cuda_runtime.h>
#include <cstdint>

// 16 lanes per group, float4 per lane; each group processes FOUR consecutive
// edges with all 20 gather LDG.128s batched up front (deep MLP per warp).
// Indices for the 4 edges load as one int4 each for src/dst.
// Gathers use L2 evict_last (node tables ~51MB pinned in 126MB L2);
// output uses evict-first streaming stores.

__device__ __forceinline__ float4 ldg_el(const float* p, uint64_t pol) {
    float4 v;
    asm volatile(
        "ld.global.nc.L2::cache_hint.v4.f32 {%0,%1,%2,%3}, [%4], %5;"
        : "=f"(v.x), "=f"(v.y), "=f"(v.z), "=f"(v.w)
        : "l"(p), "l"(pol));
    return v;
}

__global__ void __launch_bounds__(256) rpm_kernel(
    const float* __restrict__ G,
    const float* __restrict__ K,
    const float* __restrict__ Q,
    const float* __restrict__ V,
    const int* __restrict__ src,
    const int* __restrict__ dst,
    float* __restrict__ out,
    int n_edges,
    int n_nodes)
{
    uint64_t pol;
    asm("createpolicy.fractional.L2::evict_last.b64 %0, 1.0;" : "=l"(pol));

    int sub  = threadIdx.x >> 4;                       // 16-lane group in block
    int lane = threadIdx.x & 15;
    int g    = blockIdx.x * (blockDim.x >> 4) + sub;   // group id
    int ebase = g * 4;

    // Vector index loads: 4 src + 4 dst in two LDG.128 (broadcast across lanes).
    // Grid is sized so ebase+3 <= padded range; guard via clamp against n_edges.
    int4 s4, d4;
    if (ebase + 3 < n_edges) {
        s4 = reinterpret_cast<const int4*>(src)[g];
        d4 = reinterpret_cast<const int4*>(dst)[g];
    } else {
        int ec0 = min(ebase + 0, n_edges - 1);
        int ec1 = min(ebase + 1, n_edges - 1);
        int ec2 = min(ebase + 2, n_edges - 1);
        int ec3 = min(ebase + 3, n_edges - 1);
        s4 = make_int4(src[ec0], src[ec1], src[ec2], src[ec3]);
        d4 = make_int4(dst[ec0], dst[ec1], dst[ec2], dst[ec3]);
    }
    int s0 = min(max(s4.x, 0), n_nodes - 1), d0 = min(max(d4.x, 0), n_nodes - 1);
    int s1 = min(max(s4.y, 0), n_nodes - 1), d1 = min(max(d4.y, 0), n_nodes - 1);
    int s2 = min(max(s4.z, 0), n_nodes - 1), d2 = min(max(d4.z, 0), n_nodes - 1);
    int s3 = min(max(s4.w, 0), n_nodes - 1), d3 = min(max(d4.w, 0), n_nodes - 1);

    size_t l4 = (size_t)lane * 4;

    // 20 batched gathers (deep MLP).
    float4 gs0 = ldg_el(G + (size_t)s0 * 64 + l4, pol);
    float4 gd0 = ldg_el(G + (size_t)d0 * 64 + l4, pol);
    float4 ks0 = ldg_el(K + (size_t)s0 * 64 + l4, pol);
    float4 qd0 = ldg_el(Q + (size_t)d0 * 64 + l4, pol);
    float4 vs0 = ldg_el(V + (size_t)s0 * 64 + l4, pol);
    float4 gs1 = ldg_el(G + (size_t)s1 * 64 + l4, pol);
    float4 gd1 = ldg_el(G + (size_t)d1 * 64 + l4, pol);
    float4 ks1 = ldg_el(K + (size_t)s1 * 64 + l4, pol);
    float4 qd1 = ldg_el(Q + (size_t)d1 * 64 + l4, pol);
    float4 vs1 = ldg_el(V + (size_t)s1 * 64 + l4, pol);
    float4 gs2 = ldg_el(G + (size_t)s2 * 64 + l4, pol);
    float4 gd2 = ldg_el(G + (size_t)d2 * 64 + l4, pol);
    float4 ks2 = ldg_el(K + (size_t)s2 * 64 + l4, pol);
    float4 qd2 = ldg_el(Q + (size_t)d2 * 64 + l4, pol);
    float4 vs2 = ldg_el(V + (size_t)s2 * 64 + l4, pol);
    float4 gs3 = ldg_el(G + (size_t)s3 * 64 + l4, pol);
    float4 gd3 = ldg_el(G + (size_t)d3 * 64 + l4, pol);
    float4 ks3 = ldg_el(K + (size_t)s3 * 64 + l4, pol);
    float4 qd3 = ldg_el(Q + (size_t)d3 * 64 + l4, pol);
    float4 vs3 = ldg_el(V + (size_t)s3 * 64 + l4, pol);

    float dx, dy, dz, dw;
    dx = gs0.x-gd0.x; dy = gs0.y-gd0.y; dz = gs0.z-gd0.z; dw = gs0.w-gd0.w;
    float pd0 = dx*dx + dy*dy + dz*dz + dw*dw;
    float pk0 = ks0.x*qd0.x + ks0.y*qd0.y + ks0.z*qd0.z + ks0.w*qd0.w;
    dx = gs1.x-gd1.x; dy = gs1.y-gd1.y; dz = gs1.z-gd1.z; dw = gs1.w-gd1.w;
    float pd1 = dx*dx + dy*dy + dz*dz + dw*dw;
    float pk1 = ks1.x*qd1.x + ks1.y*qd1.y + ks1.z*qd1.z + ks1.w*qd1.w;
    dx = gs2.x-gd2.x; dy = gs2.y-gd2.y; dz = gs2.z-gd2.z; dw = gs2.w-gd2.w;
    float pd2 = dx*dx + dy*dy + dz*dz + dw*dw;
    float pk2 = ks2.x*qd2.x + ks2.y*qd2.y + ks2.z*qd2.z + ks2.w*qd2.w;
    dx = gs3.x-gd3.x; dy = gs3.y-gd3.y; dz = gs3.z-gd3.z; dw = gs3.w-gd3.w;
    float pd3 = dx*dx + dy*dy + dz*dz + dw*dw;
    float pk3 = ks3.x*qd3.x + ks3.y*qd3.y + ks3.z*qd3.z + ks3.w*qd3.w;

    #pragma unroll
    for (int off = 8; off > 0; off >>= 1) {
        pd0 += __shfl_xor_sync(0xFFFFFFFFu, pd0, off);
        pk0 += __shfl_xor_sync(0xFFFFFFFFu, pk0, off);
        pd1 += __shfl_xor_sync(0xFFFFFFFFu, pd1, off);
        pk1 += __shfl_xor_sync(0xFFFFFFFFu, pk1, off);
        pd2 += __shfl_xor_sync(0xFFFFFFFFu, pd2, off);
        pk2 += __shfl_xor_sync(0xFFFFFFFFu, pk2, off);
        pd3 += __shfl_xor_sync(0xFFFFFFFFu, pd3, off);
        pk3 += __shfl_xor_sync(0xFFFFFFFFu, pk3, off);
    }

    const float isd = 0.125f;  // 1/sqrt(64)
    float w0 = __expf(fminf(fmaxf(-sqrtf(pd0 + 1e-6f) * isd, -5.0f), 5.0f)
                    + fminf(fmaxf(pk0 * isd, -5.0f), 5.0f));
    float w1 = __expf(fminf(fmaxf(-sqrtf(pd1 + 1e-6f) * isd, -5.0f), 5.0f)
                    + fminf(fmaxf(pk1 * isd, -5.0f), 5.0f));
    float w2 = __expf(fminf(fmaxf(-sqrtf(pd2 + 1e-6f) * isd, -5.0f), 5.0f)
                    + fminf(fmaxf(pk2 * isd, -5.0f), 5.0f));
    float w3 = __expf(fminf(fmaxf(-sqrtf(pd3 + 1e-6f) * isd, -5.0f), 5.0f)
                    + fminf(fmaxf(pk3 * isd, -5.0f), 5.0f));

    float4* out4 = reinterpret_cast<float4*>(out);
    if (ebase + 0 < n_edges)
        __stcs(&out4[(size_t)(ebase + 0) * 16 + lane],
               make_float4(w0*vs0.x, w0*vs0.y, w0*vs0.z, w0*vs0.w));
    if (ebase + 1 < n_edges)
        __stcs(&out4[(size_t)(ebase + 1) * 16 + lane],
               make_float4(w1*vs1.x, w1*vs1.y, w1*vs1.z, w1*vs1.w));
    if (ebase + 2 < n_edges)
        __stcs(&out4[(size_t)(ebase + 2) * 16 + lane],
               make_float4(w2*vs2.x, w2*vs2.y, w2*vs2.z, w2*vs2.w));
    if (ebase + 3 < n_edges)
        __stcs(&out4[(size_t)(ebase + 3) * 16 + lane],
               make_float4(w3*vs3.x, w3*vs3.y, w3*vs3.z, w3*vs3.w));
}

extern "C" void kernel_launch(void* const* d_in, const int* in_sizes, int n_in,
                              void* d_out, int out_size) {
    const float* G = (const float*)d_in[0];
    const float* K = (const float*)d_in[1];
    const float* Q = (const float*)d_in[2];
    const float* V = (const float*)d_in[3];
    const int* src = (const int*)d_in[4];
    const int* dst = (const int*)d_in[5];
    float* out = (float*)d_out;

    int n_edges = in_sizes[4];       // src element count
    int n_nodes = in_sizes[0] / 64;  // G_h rows
    int groups_per_block = 256 / 16;            // 16 groups
    int edges_per_block = groups_per_block * 4; // 64 edges
    int blocks = (n_edges + edges_per_block - 1) / edges_per_block;
    rpm_kernel<<<blocks, 256>>>(G, K, Q, V, src, dst, out, n_edges, n_nodes);
}

// round 7
// speedup vs baseline: 1.8811x; 1.0234x over previous
#include <cuda_runtime.h>
#include <cstdint>

// 16 lanes per group, float4 per lane, 4 edges per group, 20 gathers batched.
// Reduction uses a value-folding butterfly: 8 values (pd,pk x 4 edges) reduced
// across 16 lanes in 15 shfls + packing SELs; epilogue (sqrt/exp/clamp) then
// runs ONCE per warp with each lane owning one edge's scalars.
// Gathers: L2 evict_last policy. Output: evict-first streaming stores.

__device__ __forceinline__ float4 ldg_el(const float* p, uint64_t pol) {
    float4 v;
    asm volatile(
        "ld.global.nc.L2::cache_hint.v4.f32 {%0,%1,%2,%3}, [%4], %5;"
        : "=f"(v.x), "=f"(v.y), "=f"(v.z), "=f"(v.w)
        : "l"(p), "l"(pol));
    return v;
}

#define SHX(v, off) __shfl_xor_sync(0xFFFFFFFFu, (v), (off), 16)

__global__ void __launch_bounds__(256) rpm_kernel(
    const float* __restrict__ G,
    const float* __restrict__ K,
    const float* __restrict__ Q,
    const float* __restrict__ V,
    const int* __restrict__ src,
    const int* __restrict__ dst,
    float* __restrict__ out,
    int n_edges,
    int n_nodes)
{
    uint64_t pol;
    asm("createpolicy.fractional.L2::evict_last.b64 %0, 1.0;" : "=l"(pol));

    int sub  = threadIdx.x >> 4;
    int lane = threadIdx.x & 15;
    int g    = blockIdx.x * (blockDim.x >> 4) + sub;
    int ebase = g * 4;

    int4 s4, d4;
    if (ebase + 3 < n_edges) {
        s4 = reinterpret_cast<const int4*>(src)[g];
        d4 = reinterpret_cast<const int4*>(dst)[g];
    } else {
        int ec0 = min(ebase + 0, n_edges - 1);
        int ec1 = min(ebase + 1, n_edges - 1);
        int ec2 = min(ebase + 2, n_edges - 1);
        int ec3 = min(ebase + 3, n_edges - 1);
        s4 = make_int4(src[ec0], src[ec1], src[ec2], src[ec3]);
        d4 = make_int4(dst[ec0], dst[ec1], dst[ec2], dst[ec3]);
    }

    size_t l4 = (size_t)lane * 4;

    // 20 batched gathers (deep MLP); indices trusted in [0, n_nodes).
    float4 gs0 = ldg_el(G + (size_t)s4.x * 64 + l4, pol);
    float4 gd0 = ldg_el(G + (size_t)d4.x * 64 + l4, pol);
    float4 ks0 = ldg_el(K + (size_t)s4.x * 64 + l4, pol);
    float4 qd0 = ldg_el(Q + (size_t)d4.x * 64 + l4, pol);
    float4 vs0 = ldg_el(V + (size_t)s4.x * 64 + l4, pol);
    float4 gs1 = ldg_el(G + (size_t)s4.y * 64 + l4, pol);
    float4 gd1 = ldg_el(G + (size_t)d4.y * 64 + l4, pol);
    float4 ks1 = ldg_el(K + (size_t)s4.y * 64 + l4, pol);
    float4 qd1 = ldg_el(Q + (size_t)d4.y * 64 + l4, pol);
    float4 vs1 = ldg_el(V + (size_t)s4.y * 64 + l4, pol);
    float4 gs2 = ldg_el(G + (size_t)s4.z * 64 + l4, pol);
    float4 gd2 = ldg_el(G + (size_t)d4.z * 64 + l4, pol);
    float4 ks2 = ldg_el(K + (size_t)s4.z * 64 + l4, pol);
    float4 qd2 = ldg_el(Q + (size_t)d4.z * 64 + l4, pol);
    float4 vs2 = ldg_el(V + (size_t)s4.z * 64 + l4, pol);
    float4 gs3 = ldg_el(G + (size_t)s4.w * 64 + l4, pol);
    float4 gd3 = ldg_el(G + (size_t)d4.w * 64 + l4, pol);
    float4 ks3 = ldg_el(K + (size_t)s4.w * 64 + l4, pol);
    float4 qd3 = ldg_el(Q + (size_t)d4.w * 64 + l4, pol);
    float4 vs3 = ldg_el(V + (size_t)s4.w * 64 + l4, pol);

    float dx, dy, dz, dw;
    dx = gs0.x-gd0.x; dy = gs0.y-gd0.y; dz = gs0.z-gd0.z; dw = gs0.w-gd0.w;
    float pd0 = dx*dx + dy*dy + dz*dz + dw*dw;
    float pk0 = ks0.x*qd0.x + ks0.y*qd0.y + ks0.z*qd0.z + ks0.w*qd0.w;
    dx = gs1.x-gd1.x; dy = gs1.y-gd1.y; dz = gs1.z-gd1.z; dw = gs1.w-gd1.w;
    float pd1 = dx*dx + dy*dy + dz*dz + dw*dw;
    float pk1 = ks1.x*qd1.x + ks1.y*qd1.y + ks1.z*qd1.z + ks1.w*qd1.w;
    dx = gs2.x-gd2.x; dy = gs2.y-gd2.y; dz = gs2.z-gd2.z; dw = gs2.w-gd2.w;
    float pd2 = dx*dx + dy*dy + dz*dz + dw*dw;
    float pk2 = ks2.x*qd2.x + ks2.y*qd2.y + ks2.z*qd2.z + ks2.w*qd2.w;
    dx = gs3.x-gd3.x; dy = gs3.y-gd3.y; dz = gs3.z-gd3.z; dw = gs3.w-gd3.w;
    float pd3 = dx*dx + dy*dy + dz*dz + dw*dw;
    float pk3 = ks3.x*qd3.x + ks3.y*qd3.y + ks3.z*qd3.z + ks3.w*qd3.w;

    // ---- folding reduction: 8 values over 16 lanes ----
    // Level 0 (offset 8): 8 shfls, then fold pd/pk by lane bit3.
    pd0 += SHX(pd0, 8);  pk0 += SHX(pk0, 8);
    pd1 += SHX(pd1, 8);  pk1 += SHX(pk1, 8);
    pd2 += SHX(pd2, 8);  pk2 += SHX(pk2, 8);
    pd3 += SHX(pd3, 8);  pk3 += SHX(pk3, 8);
    bool h8 = (lane & 8) != 0;
    float y0 = h8 ? pk0 : pd0;
    float y1 = h8 ? pk1 : pd1;
    float y2 = h8 ? pk2 : pd2;
    float y3 = h8 ? pk3 : pd3;
    // Level 1 (offset 4): 4 shfls, fold edge-pairs by lane bit2.
    y0 += SHX(y0, 4);  y1 += SHX(y1, 4);  y2 += SHX(y2, 4);  y3 += SHX(y3, 4);
    bool h4 = (lane & 4) != 0;
    float z0 = h4 ? y1 : y0;     // edges 0/1 by bit2
    float z1 = h4 ? y3 : y2;     // edges 2/3 by bit2
    // Level 2 (offset 2): 2 shfls, fold by lane bit1.
    z0 += SHX(z0, 2);  z1 += SHX(z1, 2);
    bool h2 = (lane & 2) != 0;
    float u = h2 ? z1 : z0;      // edge = 2*bit1 + bit2, type = bit3
    // Level 3 (offset 1): final sum.
    u += SHX(u, 1);
    // Exchange pd<->pk between bit3 halves: every lane gets its edge's pair.
    float t = SHX(u, 8);
    float pdv = h8 ? t : u;
    float pkv = h8 ? u : t;

    // Epilogue once per warp; lane owns edge (2*bit1 + bit2).
    const float isd = 0.125f;  // 1/sqrt(64)
    float a = fminf(fmaxf(-sqrtf(pdv + 1e-6f) * isd, -5.0f), 5.0f);
    float b = fminf(fmaxf(pkv * isd, -5.0f), 5.0f);
    float w = __expf(a + b);

    // Broadcast per-edge weights: edge e lives in lane ((e&1)<<2)|((e>>1)<<1).
    float w0 = __shfl_sync(0xFFFFFFFFu, w, 0, 16);
    float w1 = __shfl_sync(0xFFFFFFFFu, w, 4, 16);
    float w2 = __shfl_sync(0xFFFFFFFFu, w, 2, 16);
    float w3 = __shfl_sync(0xFFFFFFFFu, w, 6, 16);

    float4* out4 = reinterpret_cast<float4*>(out);
    if (ebase + 0 < n_edges)
        __stcs(&out4[(size_t)(ebase + 0) * 16 + lane],
               make_float4(w0*vs0.x, w0*vs0.y, w0*vs0.z, w0*vs0.w));
    if (ebase + 1 < n_edges)
        __stcs(&out4[(size_t)(ebase + 1) * 16 + lane],
               make_float4(w1*vs1.x, w1*vs1.y, w1*vs1.z, w1*vs1.w));
    if (ebase + 2 < n_edges)
        __stcs(&out4[(size_t)(ebase + 2) * 16 + lane],
               make_float4(w2*vs2.x, w2*vs2.y, w2*vs2.z, w2*vs2.w));
    if (ebase + 3 < n_edges)
        __stcs(&out4[(size_t)(ebase + 3) * 16 + lane],
               make_float4(w3*vs3.x, w3*vs3.y, w3*vs3.z, w3*vs3.w));
}

extern "C" void kernel_launch(void* const* d_in, const int* in_sizes, int n_in,
                              void* d_out, int out_size) {
    const float* G = (const float*)d_in[0];
    const float* K = (const float*)d_in[1];
    const float* Q = (const float*)d_in[2];
    const float* V = (const float*)d_in[3];
    const int* src = (const int*)d_in[4];
    const int* dst = (const int*)d_in[5];
    float* out = (float*)d_out;

    int n_edges = in_sizes[4];
    int n_nodes = in_sizes[0] / 64;
    int groups_per_block = 256 / 16;
    int edges_per_block = groups_per_block * 4;   // 64 edges/block
    int blocks = (n_edges + edges_per_block - 1) / edges_per_block;
    rpm_kernel<<<blocks, 256>>>(G, K, Q, V, src, dst, out, n_edges, n_nodes);
}